// round 15
// baseline (speedup 1.0000x reference)
#include <cuda_runtime.h>
#include <cuda_bf16.h>
#include <stdint.h>

#define DIMN 768
#define NH   16
#define DK   48
#define TT   2048
#define BH   64
#define MM   8192
#define QSCALE 0.14433756729740643f

typedef __nv_bfloat16 bf16;

// ---------------- scratch (__device__ globals) ----------------
__device__ __align__(256) bf16 g_xhi[MM*DIMN],  g_xlo[MM*DIMN];
__device__ __align__(256) bf16 g_wthi[4*DIMN*DIMN], g_wtlo[4*DIMN*DIMN];   // W^T [w][n][k]
__device__ __align__(256) bf16 g_qhi[BH*TT*DK], g_qlo[BH*TT*DK];           // [bh][t][d], pre-scaled
__device__ __align__(256) bf16 g_khi[BH*TT*DK], g_klo[BH*TT*DK];           // [bh][t][d]
__device__ __align__(256) bf16 g_vthi[BH*DK*TT], g_vtlo[BH*DK*TT];         // [bh][d][t]  (V^T)
__device__ __align__(256) bf16 g_ohi[MM*DIMN],  g_olo[MM*DIMN];            // attn out split

// ---------------- helpers ----------------
#define SW(o) ((o) ^ (((o) >> 3) & 0x70))   // SW128 swizzle, byte offsets

__device__ __forceinline__ uint32_t smem_u32(const void* p) {
    uint32_t r;
    asm("{ .reg .u64 t; cvta.to.shared.u64 t, %1; cvt.u32.u64 %0, t; }" : "=r"(r) : "l"(p));
    return r;
}
__device__ __forceinline__ uint32_t pack_bf16x2(float lo, float hi) {
    uint32_t r; asm("cvt.rn.bf16x2.f32 %0, %1, %2;" : "=r"(r) : "f"(hi), "f"(lo)); return r;
}
__device__ __forceinline__ float bf16round(float x) {
    return __bfloat162float(__float2bfloat16(x));
}
__device__ __forceinline__ void mma_bf16(float* c, const uint32_t* a, const uint32_t* b) {
    asm volatile("mma.sync.aligned.m16n8k16.row.col.f32.bf16.bf16.f32 "
        "{%0,%1,%2,%3}, {%4,%5,%6,%7}, {%8,%9}, {%0,%1,%2,%3};"
        : "+f"(c[0]), "+f"(c[1]), "+f"(c[2]), "+f"(c[3])
        : "r"(a[0]), "r"(a[1]), "r"(a[2]), "r"(a[3]), "r"(b[0]), "r"(b[1]));
}
__device__ __forceinline__ void ldsm_x4(uint32_t* r, uint32_t addr) {
    asm volatile("ldmatrix.sync.aligned.m8n8.x4.shared.b16 {%0,%1,%2,%3}, [%4];"
        : "=r"(r[0]), "=r"(r[1]), "=r"(r[2]), "=r"(r[3]) : "r"(addr));
}
__device__ __forceinline__ uint32_t ldsm_addr(uint32_t sbu, int lane, int row_base, int pitch, int kbyte) {
    const int r = row_base + (lane & 7) + ((lane >> 3) & 1) * 8;
    const int cb = kbyte + ((lane >> 4) * 16);
    return sbu + SW((uint32_t)(r * pitch + cb));
}
#define CPA16(dst, src) asm volatile("cp.async.cg.shared.global [%0], [%1], 16;" :: "r"(dst), "l"(src))
#define CPC()   asm volatile("cp.async.commit_group;" ::: "memory")
#define CPW(n)  asm volatile("cp.async.wait_group %0;" :: "n"(n) : "memory")

// ---------------- split / transpose prep ----------------
__global__ void split_x_kernel(const float* __restrict__ x, bf16* __restrict__ hi, bf16* __restrict__ lo) {
    int i = (blockIdx.x * 256 + threadIdx.x) * 4;
    float4 v = *reinterpret_cast<const float4*>(x + i);
    float h0 = bf16round(v.x), h1 = bf16round(v.y), h2 = bf16round(v.z), h3 = bf16round(v.w);
    uint2 H = make_uint2(pack_bf16x2(h0, h1), pack_bf16x2(h2, h3));
    uint2 L = make_uint2(pack_bf16x2(v.x - h0, v.y - h1), pack_bf16x2(v.z - h2, v.w - h3));
    *reinterpret_cast<uint2*>(hi + i) = H;
    *reinterpret_cast<uint2*>(lo + i) = L;
}

__global__ void wsplit_kernel(const float* __restrict__ W0, const float* __restrict__ W1,
                              const float* __restrict__ W2, const float* __restrict__ W3,
                              bf16* __restrict__ thi, bf16* __restrict__ tlo) {
    __shared__ float t[32][33];
    const int z = blockIdx.z;
    const float* W = (z == 0) ? W0 : (z == 1) ? W1 : (z == 2) ? W2 : W3;
    bf16* th = thi + (size_t)z * DIMN * DIMN;
    bf16* tl = tlo + (size_t)z * DIMN * DIMN;
    int k0 = blockIdx.y * 32, n0 = blockIdx.x * 32;
    int tx = threadIdx.x, ty = threadIdx.y;
    #pragma unroll
    for (int i = 0; i < 4; i++)
        t[ty + 8 * i][tx] = W[(size_t)(k0 + ty + 8 * i) * DIMN + n0 + tx];
    __syncthreads();
    #pragma unroll
    for (int i = 0; i < 4; i++) {
        float v = t[tx][ty + 8 * i];
        float h = bf16round(v);
        size_t idx = (size_t)(n0 + ty + 8 * i) * DIMN + k0 + tx;
        th[idx] = __float2bfloat16(h);
        tl[idx] = __float2bfloat16(v - h);
    }
}

// ---------------- pipelined mma GEMM: C[128x128] = A[128x768] * B^T ----------
#define GEMM_SMEM (1024 + 2*65536)

__global__ __launch_bounds__(256)
void gemm_mma(const bf16* __restrict__ Ahi, const bf16* __restrict__ Alo,
              const bf16* __restrict__ WThi, const bf16* __restrict__ WTlo,
              const float* __restrict__ b0, const float* __restrict__ b1,
              const float* __restrict__ b2, int mode_in,
              float* __restrict__ outf,
              bf16* __restrict__ o0h, bf16* __restrict__ o0l,
              bf16* __restrict__ o1h, bf16* __restrict__ o1l,
              bf16* __restrict__ o2h, bf16* __restrict__ o2l)
{
    extern __shared__ char sm[];
    const uint32_t sm0 = smem_u32(sm);
    const uint32_t sb  = (sm0 + 1023) & ~1023u;

    const int z = blockIdx.z;
    const int mode = (mode_in < 0) ? z : mode_in;
    const size_t WSZ = (size_t)DIMN * DIMN;
    const bf16* Bhi = WThi + (mode_in < 0 ? (size_t)z * WSZ : 0);
    const bf16* Blo = WTlo + (mode_in < 0 ? (size_t)z * WSZ : 0);
    const float* bias = (mode == 0) ? b0 : (mode == 1) ? b1 : b2;
    bf16* ohi = (z == 0) ? o0h : (z == 1) ? o1h : o2h;
    bf16* olo = (z == 0) ? o0l : (z == 1) ? o1l : o2l;

    const int tid = threadIdx.x, wid = tid >> 5, lane = tid & 31;
    const int gid = lane >> 2, t4 = lane & 3;
    const int wm = wid & 1, wn = wid >> 1;
    const int m0 = blockIdx.y * 128, n0 = blockIdx.x * 128;

    const char* srcs[4] = { (const char*)(Ahi + (size_t)m0 * DIMN), (const char*)(Alo + (size_t)m0 * DIMN),
                            (const char*)(Bhi + (size_t)n0 * DIMN), (const char*)(Blo + (size_t)n0 * DIMN) };

    #define GPL(s, sel) (1024u + (uint32_t)(s) * 65536u + (uint32_t)(sel) * 16384u)

    #pragma unroll
    for (int i = 0; i < 16; i++) {
        const int sel = i >> 2;
        const int cidx = (i & 3) * 256 + tid;
        const int row = cidx >> 3, cc = (cidx & 7) * 16;
        CPA16(sb + GPL(0, sel) + SW(row * 128 + cc),
              srcs[sel] + (size_t)row * (DIMN * 2) + cc);
    }
    CPC();

    float c[4][4][4] = {};

    for (int ch = 0; ch < 12; ch++) {
        if (ch < 11) {
            const int kb = (ch + 1) * 128;
            const int s = (ch + 1) & 1;
            #pragma unroll
            for (int i = 0; i < 16; i++) {
                const int sel = i >> 2;
                const int cidx = (i & 3) * 256 + tid;
                const int row = cidx >> 3, cc = (cidx & 7) * 16;
                CPA16(sb + GPL(s, sel) + SW(row * 128 + cc),
                      srcs[sel] + (size_t)row * (DIMN * 2) + kb + cc);
            }
            CPC();
            CPW(1);
        } else {
            CPW(0);
        }
        __syncthreads();

        const uint32_t pA = sb + GPL(ch & 1, 0), pAl = sb + GPL(ch & 1, 1);
        const uint32_t pB = sb + GPL(ch & 1, 2), pBl = sb + GPL(ch & 1, 3);
        #pragma unroll
        for (int ks = 0; ks < 4; ks++) {
            const int kbyt = ks * 32;
            uint32_t aH[4][4], aL[4][4];
            #pragma unroll
            for (int mt = 0; mt < 4; mt++) {
                const int rb = wm * 64 + mt * 16;
                ldsm_x4(aH[mt], ldsm_addr(pA,  lane, rb, 128, kbyt));
                ldsm_x4(aL[mt], ldsm_addr(pAl, lane, rb, 128, kbyt));
            }
            uint32_t bH[4][2], bL[4][2];
            #pragma unroll
            for (int np = 0; np < 2; np++) {
                uint32_t t0[4], t1[4];
                const int rb = wn * 32 + np * 16;
                ldsm_x4(t0, ldsm_addr(pB,  lane, rb, 128, kbyt));
                ldsm_x4(t1, ldsm_addr(pBl, lane, rb, 128, kbyt));
                bH[2*np][0] = t0[0]; bH[2*np][1] = t0[2];
                bH[2*np+1][0] = t0[1]; bH[2*np+1][1] = t0[3];
                bL[2*np][0] = t1[0]; bL[2*np][1] = t1[2];
                bL[2*np+1][0] = t1[1]; bL[2*np+1][1] = t1[3];
            }
            #pragma unroll
            for (int mt = 0; mt < 4; mt++)
                #pragma unroll
                for (int nt = 0; nt < 4; nt++) {
                    mma_bf16(c[mt][nt], aH[mt], bH[nt]);
                    mma_bf16(c[mt][nt], aH[mt], bL[nt]);
                    mma_bf16(c[mt][nt], aL[mt], bH[nt]);
                }
        }
        __syncthreads();
    }

    #pragma unroll
    for (int mt = 0; mt < 4; mt++)
        #pragma unroll
        for (int nt = 0; nt < 4; nt++)
            #pragma unroll
            for (int i = 0; i < 4; i++) {
                const int m = m0 + wm * 64 + mt * 16 + gid + (i >> 1) * 8;
                const int n = n0 + wn * 32 + nt * 8 + t4 * 2 + (i & 1);
                float v = c[mt][nt][i] + bias[n];
                if (mode == 3) {
                    outf[(size_t)m * DIMN + n] = v;
                } else {
                    if (mode == 0) v *= QSCALE;
                    const int b = m >> 11, t = m & (TT - 1);
                    const int h = n / DK, d = n - h * DK;
                    size_t idx = (mode == 2)
                        ? ((size_t)(b * NH + h) * DK + d) * TT + t
                        : ((size_t)(b * NH + h) * TT + t) * DK + d;
                    float hf = bf16round(v);
                    ohi[idx] = __float2bfloat16(hf);
                    olo[idx] = __float2bfloat16(v - hf);
                }
            }
}

// ---------------- pipelined mma flash attention (KTILE=64, 2 CTAs/SM) ------
// smem: rsum[128][2] @0; Q hi/lo @1024/@17408 (16KB each); KV stages @33792 (2 x 28KB)
//   stage: KH +0 (8K), KL +8192, VH +16384 (6K, pitch 128), VL +22528
#define ATTN_SMEM (33792 + 2*28672)
#define OST(s) (33792u + (uint32_t)(s) * 28672u)

__device__ __forceinline__ void stage_kv(uint32_t sb, uint32_t ost, int bh, int kt, int tid) {
    const char* kh = (const char*)(g_khi + ((size_t)bh * TT + kt * 64) * DK);
    const char* kl = (const char*)(g_klo + ((size_t)bh * TT + kt * 64) * DK);
    const char* vh = (const char*)(g_vthi + (size_t)bh * DK * TT + (size_t)kt * 64);
    const char* vl = (const char*)(g_vtlo + (size_t)bh * DK * TT + (size_t)kt * 64);
    #pragma unroll
    for (int i = 0; i < 6; i++) {
        const int id = i * 256 + tid;          // 0..1535
        if (id < 768) {                        // K planes: 64 rows x 96B (6 chunks)
            const char* src = (id < 384) ? kh : kl;
            const uint32_t dp = (id < 384) ? 0u : 8192u;
            const int c2 = (id < 384) ? id : id - 384;
            const int row = c2 / 6, cc = (c2 % 6) * 16;
            CPA16(sb + ost + dp + SW(row * 128 + cc), src + (size_t)row * (DK * 2) + cc);
        } else {                               // V^T planes: 48 rows x 128B (8 chunks)
            const int vid = id - 768;
            const char* src = (vid < 384) ? vh : vl;
            const uint32_t dp = (vid < 384) ? 16384u : 22528u;
            const int c2 = (vid < 384) ? vid : vid - 384;
            const int row = c2 >> 3, cc = (c2 & 7) * 16;
            CPA16(sb + ost + dp + SW(row * 128 + cc), src + (size_t)row * (TT * 2) + cc);
        }
    }
}

__global__ __launch_bounds__(256)
void attn_mma()
{
    extern __shared__ char sm[];
    const uint32_t sm0 = smem_u32(sm);
    const uint32_t sb  = (sm0 + 1023) & ~1023u;
    char* sbase = sm + (sb - sm0);
    const uint32_t oQH = 1024, oQL = 17408;

    const int tid = threadIdx.x, wid = tid >> 5, lane = tid & 31;
    const int gid = lane >> 2, t4 = lane & 3;
    const int rg = wid & 3, cg = wid >> 2;
    const int bh = blockIdx.y, q0 = blockIdx.x * 128;
    const int b = bh >> 4, h = bh & 15;

    {
        const char* qh = (const char*)(g_qhi + ((size_t)bh * TT + q0) * DK);
        const char* ql = (const char*)(g_qlo + ((size_t)bh * TT + q0) * DK);
        #pragma unroll
        for (int i = 0; i < 6; i++) {
            const int id = i * 256 + tid;
            const char* src = (id < 768) ? qh : ql;
            const uint32_t dp = (id < 768) ? oQH : oQL;
            const int c2 = (id < 768) ? id : id - 768;
            const int row = c2 / 6, cc = (c2 % 6) * 16;
            CPA16(sb + dp + SW(row * 128 + cc), src + (size_t)row * (DK * 2) + cc);
        }
        stage_kv(sb, OST(0), bh, 0, tid);
        CPC();
    }

    float co[2][6][4] = {};
    float lsum[2][2] = {};

    for (int kt = 0; kt < 32; kt++) {
        if (kt < 31) {
            stage_kv(sb, OST((kt + 1) & 1), bh, kt + 1, tid);
            CPC();
            CPW(1);
        } else {
            CPW(0);
        }
        __syncthreads();

        const uint32_t oKH = sb + OST(kt & 1), oKL = oKH + 8192;
        const uint32_t oVH = oKH + 16384, oVL = oKH + 22528;

        // S = Q K^T over this warp's 32 keys
        float cs[2][4][4] = {};
        #pragma unroll
        for (int ks = 0; ks < 3; ks++) {
            const int kbyt = ks * 32;
            uint32_t qHf[2][4], qLf[2][4];
            #pragma unroll
            for (int mt = 0; mt < 2; mt++) {
                const int rb = rg * 32 + mt * 16;
                ldsm_x4(qHf[mt], ldsm_addr(sb + oQH, lane, rb, 128, kbyt));
                ldsm_x4(qLf[mt], ldsm_addr(sb + oQL, lane, rb, 128, kbyt));
            }
            #pragma unroll
            for (int np = 0; np < 2; np++) {           // 2 x4-loads cover 4 n-tiles
                uint32_t t0[4], t1[4];
                const int rb = cg * 32 + np * 16;
                ldsm_x4(t0, ldsm_addr(oKH, lane, rb, 128, kbyt));
                ldsm_x4(t1, ldsm_addr(oKL, lane, rb, 128, kbyt));
                uint32_t bHf0[2] = { t0[0], t0[2] }, bHf1[2] = { t0[1], t0[3] };
                uint32_t bLf0[2] = { t1[0], t1[2] }, bLf1[2] = { t1[1], t1[3] };
                #pragma unroll
                for (int mt = 0; mt < 2; mt++) {
                    mma_bf16(cs[mt][2*np],   qHf[mt], bHf0);
                    mma_bf16(cs[mt][2*np],   qHf[mt], bLf0);
                    mma_bf16(cs[mt][2*np],   qLf[mt], bHf0);
                    mma_bf16(cs[mt][2*np+1], qHf[mt], bHf1);
                    mma_bf16(cs[mt][2*np+1], qHf[mt], bLf1);
                    mma_bf16(cs[mt][2*np+1], qLf[mt], bHf1);
                }
            }
        }

        // p = exp(s); row partial sums
        #pragma unroll
        for (int mt = 0; mt < 2; mt++)
            #pragma unroll
            for (int nt = 0; nt < 4; nt++)
                #pragma unroll
                for (int i = 0; i < 4; i++) {
                    float e = __expf(cs[mt][nt][i]);
                    cs[mt][nt][i] = e;
                    lsum[mt][i >> 1] += e;
                }

        // O += P V  (this warp's 32-key slice of the K-dim)
        #pragma unroll
        for (int kk = 0; kk < 2; kk++) {
            uint32_t pH[2][4], pL[2][4];
            #pragma unroll
            for (int mt = 0; mt < 2; mt++)
                #pragma unroll
                for (int half = 0; half < 2; half++) {
                    const float e0 = cs[mt][2 * kk + half][0], e1 = cs[mt][2 * kk + half][1];
                    const float e2 = cs[mt][2 * kk + half][2], e3 = cs[mt][2 * kk + half][3];
                    const float h0 = bf16round(e0), h1 = bf16round(e1);
                    const float h2 = bf16round(e2), h3 = bf16round(e3);
                    pH[mt][half * 2 + 0] = pack_bf16x2(h0, h1);
                    pH[mt][half * 2 + 1] = pack_bf16x2(h2, h3);
                    pL[mt][half * 2 + 0] = pack_bf16x2(e0 - h0, e1 - h1);
                    pL[mt][half * 2 + 1] = pack_bf16x2(e2 - h2, e3 - h3);
                }
            const int kbyt = cg * 64 + kk * 32;       // V^T pitch 128, key j at byte 2j
            #pragma unroll
            for (int np = 0; np < 3; np++) {
                uint32_t t0[4], t1[4];
                const int rb = np * 16;
                ldsm_x4(t0, ldsm_addr(oVH, lane, rb, 128, kbyt));
                ldsm_x4(t1, ldsm_addr(oVL, lane, rb, 128, kbyt));
                uint32_t vHf0[2] = { t0[0], t0[2] }, vHf1[2] = { t0[1], t0[3] };
                uint32_t vLf0[2] = { t1[0], t1[2] }, vLf1[2] = { t1[1], t1[3] };
                #pragma unroll
                for (int mt = 0; mt < 2; mt++) {
                    mma_bf16(co[mt][2*np],   pH[mt], vHf0);
                    mma_bf16(co[mt][2*np],   pH[mt], vLf0);
                    mma_bf16(co[mt][2*np],   pL[mt], vHf0);
                    mma_bf16(co[mt][2*np+1], pH[mt], vHf1);
                    mma_bf16(co[mt][2*np+1], pH[mt], vLf1);
                    mma_bf16(co[mt][2*np+1], pL[mt], vHf1);
                }
            }
        }
        __syncthreads();
    }

    // cross-warp reductions
    #pragma unroll
    for (int mt = 0; mt < 2; mt++)
        #pragma unroll
        for (int hf = 0; hf < 2; hf++) {
            float v = lsum[mt][hf];
            v += __shfl_xor_sync(0xffffffffu, v, 1);
            v += __shfl_xor_sync(0xffffffffu, v, 2);
            lsum[mt][hf] = v;
        }
    float* rsum = reinterpret_cast<float*>(sbase);            // [128][2]
    if (t4 == 0)
        #pragma unroll
        for (int mt = 0; mt < 2; mt++)
            #pragma unroll
            for (int hf = 0; hf < 2; hf++)
                rsum[(rg * 32 + mt * 16 + hf * 8 + gid) * 2 + cg] = lsum[mt][hf];

    float* osum = reinterpret_cast<float*>(sbase + OST(0));   // [128][48] = 24KB < 28KB stage
    if (cg == 1)
        #pragma unroll
        for (int mt = 0; mt < 2; mt++)
            #pragma unroll
            for (int nt = 0; nt < 6; nt++)
                #pragma unroll
                for (int i = 0; i < 4; i++) {
                    const int row = rg * 32 + mt * 16 + (i >> 1) * 8 + gid;
                    const int col = nt * 8 + t4 * 2 + (i & 1);
                    osum[row * 48 + col] = co[mt][nt][i];
                }
    __syncthreads();

    if (cg == 0)
        #pragma unroll
        for (int mt = 0; mt < 2; mt++)
            #pragma unroll
            for (int nt = 0; nt < 6; nt++)
                #pragma unroll
                for (int i = 0; i < 4; i++) {
                    const int row = rg * 32 + mt * 16 + (i >> 1) * 8 + gid;
                    const int col = nt * 8 + t4 * 2 + (i & 1);
                    const float inv = 1.0f / (rsum[row * 2] + rsum[row * 2 + 1]);
                    const float v = (co[mt][nt][i] + osum[row * 48 + col]) * inv;
                    const size_t idx = ((size_t)(b * TT + q0 + row)) * DIMN + h * DK + col;
                    const float hfv = bf16round(v);
                    g_ohi[idx] = __float2bfloat16(hfv);
                    g_olo[idx] = __float2bfloat16(v - hfv);
                }
}

// ---------------- host launch ----------------
extern "C" void kernel_launch(void* const* d_in, const int* in_sizes, int n_in,
                              void* d_out, int out_size)
{
    const float* x  = (const float*)d_in[0];
    const float* Wq = (const float*)d_in[1];  const float* bq = (const float*)d_in[2];
    const float* Wk = (const float*)d_in[3];  const float* bk = (const float*)d_in[4];
    const float* Wv = (const float*)d_in[5];  const float* bv = (const float*)d_in[6];
    const float* Wp = (const float*)d_in[7];  const float* bp = (const float*)d_in[8];
    float* out = (float*)d_out;

    bf16 *xhi,*xlo,*wthi,*wtlo,*qhi,*qlo,*khi,*klo,*vthi,*vtlo,*ohi,*olo;
    cudaGetSymbolAddress((void**)&xhi, g_xhi);   cudaGetSymbolAddress((void**)&xlo, g_xlo);
    cudaGetSymbolAddress((void**)&wthi, g_wthi); cudaGetSymbolAddress((void**)&wtlo, g_wtlo);
    cudaGetSymbolAddress((void**)&qhi, g_qhi);   cudaGetSymbolAddress((void**)&qlo, g_qlo);
    cudaGetSymbolAddress((void**)&khi, g_khi);   cudaGetSymbolAddress((void**)&klo, g_klo);
    cudaGetSymbolAddress((void**)&vthi, g_vthi); cudaGetSymbolAddress((void**)&vtlo, g_vtlo);
    cudaGetSymbolAddress((void**)&ohi, g_ohi);   cudaGetSymbolAddress((void**)&olo, g_olo);

    cudaFuncSetAttribute(gemm_mma, cudaFuncAttributeMaxDynamicSharedMemorySize, GEMM_SMEM);
    cudaFuncSetAttribute(attn_mma, cudaFuncAttributeMaxDynamicSharedMemorySize, ATTN_SMEM);

    split_x_kernel<<<MM * DIMN / 1024, 256>>>(x, xhi, xlo);
    dim3 wg(24, 24, 4), wb(32, 8);
    wsplit_kernel<<<wg, wb>>>(Wq, Wk, Wv, Wp, wthi, wtlo);

    dim3 qkv_grid(DIMN / 128, MM / 128, 3);
    gemm_mma<<<qkv_grid, 256, GEMM_SMEM>>>(xhi, xlo, wthi, wtlo,
                                           bq, bk, bv, -1, nullptr,
                                           qhi, qlo, khi, klo, vthi, vtlo);

    attn_mma<<<dim3(TT / 128, BH), 256, ATTN_SMEM>>>();

    const size_t WSZ = (size_t)DIMN * DIMN;
    dim3 proj_grid(DIMN / 128, MM / 128, 1);
    gemm_mma<<<proj_grid, 256, GEMM_SMEM>>>(ohi, olo, wthi + 3 * WSZ, wtlo + 3 * WSZ,
                                            bp, bp, bp, 3, out,
                                            nullptr, nullptr, nullptr, nullptr, nullptr, nullptr);
}

// round 17
// speedup vs baseline: 1.0651x; 1.0651x over previous
#include <cuda_runtime.h>
#include <cuda_bf16.h>
#include <stdint.h>

#define DIMN 768
#define NH   16
#define DK   48
#define TT   2048
#define BH   64
#define MM   8192
#define QSCALE 0.14433756729740643f

typedef __nv_bfloat16 bf16;

// ---------------- scratch (__device__ globals) ----------------
__device__ __align__(256) bf16 g_xhi[MM*DIMN],  g_xlo[MM*DIMN];
__device__ __align__(256) bf16 g_wthi[4*DIMN*DIMN], g_wtlo[4*DIMN*DIMN];   // W^T [w][n][k]
__device__ __align__(256) bf16 g_qhi[BH*TT*DK], g_qlo[BH*TT*DK];           // [bh][t][d], pre-scaled
__device__ __align__(256) bf16 g_khi[BH*TT*DK], g_klo[BH*TT*DK];           // [bh][t][d]
__device__ __align__(256) bf16 g_vthi[BH*DK*TT], g_vtlo[BH*DK*TT];         // [bh][d][t]  (V^T)
__device__ __align__(256) bf16 g_ohi[MM*DIMN],  g_olo[MM*DIMN];            // attn out split

// ---------------- helpers ----------------
#define SW(o) ((o) ^ (((o) >> 3) & 0x70))   // SW128 swizzle, byte offsets

__device__ __forceinline__ uint32_t smem_u32(const void* p) {
    uint32_t r;
    asm("{ .reg .u64 t; cvta.to.shared.u64 t, %1; cvt.u32.u64 %0, t; }" : "=r"(r) : "l"(p));
    return r;
}
__device__ __forceinline__ uint32_t pack_bf16x2(float lo, float hi) {
    uint32_t r; asm("cvt.rn.bf16x2.f32 %0, %1, %2;" : "=r"(r) : "f"(hi), "f"(lo)); return r;
}
__device__ __forceinline__ float bf16round(float x) {
    return __bfloat162float(__float2bfloat16(x));
}
__device__ __forceinline__ void mma_bf16(float* c, const uint32_t* a, const uint32_t* b) {
    asm volatile("mma.sync.aligned.m16n8k16.row.col.f32.bf16.bf16.f32 "
        "{%0,%1,%2,%3}, {%4,%5,%6,%7}, {%8,%9}, {%0,%1,%2,%3};"
        : "+f"(c[0]), "+f"(c[1]), "+f"(c[2]), "+f"(c[3])
        : "r"(a[0]), "r"(a[1]), "r"(a[2]), "r"(a[3]), "r"(b[0]), "r"(b[1]));
}
__device__ __forceinline__ void ldsm_x4(uint32_t* r, uint32_t addr) {
    asm volatile("ldmatrix.sync.aligned.m8n8.x4.shared.b16 {%0,%1,%2,%3}, [%4];"
        : "=r"(r[0]), "=r"(r[1]), "=r"(r[2]), "=r"(r[3]) : "r"(addr));
}
__device__ __forceinline__ uint32_t ldsm_addr(uint32_t sbu, int lane, int row_base, int pitch, int kbyte) {
    const int r = row_base + (lane & 7) + ((lane >> 3) & 1) * 8;
    const int cb = kbyte + ((lane >> 4) * 16);
    return sbu + SW((uint32_t)(r * pitch + cb));
}
#define CPA16(dst, src) asm volatile("cp.async.cg.shared.global [%0], [%1], 16;" :: "r"(dst), "l"(src))
#define CPC()   asm volatile("cp.async.commit_group;" ::: "memory")
#define CPW(n)  asm volatile("cp.async.wait_group %0;" :: "n"(n) : "memory")

// ---------------- split / transpose prep ----------------
__global__ void split_x_kernel(const float* __restrict__ x, bf16* __restrict__ hi, bf16* __restrict__ lo) {
    int i = (blockIdx.x * 256 + threadIdx.x) * 4;
    float4 v = *reinterpret_cast<const float4*>(x + i);
    float h0 = bf16round(v.x), h1 = bf16round(v.y), h2 = bf16round(v.z), h3 = bf16round(v.w);
    uint2 H = make_uint2(pack_bf16x2(h0, h1), pack_bf16x2(h2, h3));
    uint2 L = make_uint2(pack_bf16x2(v.x - h0, v.y - h1), pack_bf16x2(v.z - h2, v.w - h3));
    *reinterpret_cast<uint2*>(hi + i) = H;
    *reinterpret_cast<uint2*>(lo + i) = L;
}

__global__ void wsplit_kernel(const float* __restrict__ W0, const float* __restrict__ W1,
                              const float* __restrict__ W2, const float* __restrict__ W3,
                              bf16* __restrict__ thi, bf16* __restrict__ tlo) {
    __shared__ float t[32][33];
    const int z = blockIdx.z;
    const float* W = (z == 0) ? W0 : (z == 1) ? W1 : (z == 2) ? W2 : W3;
    bf16* th = thi + (size_t)z * DIMN * DIMN;
    bf16* tl = tlo + (size_t)z * DIMN * DIMN;
    int k0 = blockIdx.y * 32, n0 = blockIdx.x * 32;
    int tx = threadIdx.x, ty = threadIdx.y;
    #pragma unroll
    for (int i = 0; i < 4; i++)
        t[ty + 8 * i][tx] = W[(size_t)(k0 + ty + 8 * i) * DIMN + n0 + tx];
    __syncthreads();
    #pragma unroll
    for (int i = 0; i < 4; i++) {
        float v = t[tx][ty + 8 * i];
        float h = bf16round(v);
        size_t idx = (size_t)(n0 + ty + 8 * i) * DIMN + k0 + tx;
        th[idx] = __float2bfloat16(h);
        tl[idx] = __float2bfloat16(v - h);
    }
}

// ---------------- pipelined mma GEMM: C[128x128] = A[128x768] * B^T ----------
#define GEMM_SMEM (1024 + 2*65536)

__global__ __launch_bounds__(256)
void gemm_mma(const bf16* __restrict__ Ahi, const bf16* __restrict__ Alo,
              const bf16* __restrict__ WThi, const bf16* __restrict__ WTlo,
              const float* __restrict__ b0, const float* __restrict__ b1,
              const float* __restrict__ b2, int mode_in,
              float* __restrict__ outf,
              bf16* __restrict__ o0h, bf16* __restrict__ o0l,
              bf16* __restrict__ o1h, bf16* __restrict__ o1l,
              bf16* __restrict__ o2h, bf16* __restrict__ o2l)
{
    extern __shared__ char sm[];
    const uint32_t sm0 = smem_u32(sm);
    const uint32_t sb  = (sm0 + 1023) & ~1023u;

    const int z = blockIdx.z;
    const int mode = (mode_in < 0) ? z : mode_in;
    const size_t WSZ = (size_t)DIMN * DIMN;
    const bf16* Bhi = WThi + (mode_in < 0 ? (size_t)z * WSZ : 0);
    const bf16* Blo = WTlo + (mode_in < 0 ? (size_t)z * WSZ : 0);
    const float* bias = (mode == 0) ? b0 : (mode == 1) ? b1 : b2;
    bf16* ohi = (z == 0) ? o0h : (z == 1) ? o1h : o2h;
    bf16* olo = (z == 0) ? o0l : (z == 1) ? o1l : o2l;

    const int tid = threadIdx.x, wid = tid >> 5, lane = tid & 31;
    const int gid = lane >> 2, t4 = lane & 3;
    const int wm = wid & 1, wn = wid >> 1;
    const int m0 = blockIdx.y * 128, n0 = blockIdx.x * 128;

    const char* srcs[4] = { (const char*)(Ahi + (size_t)m0 * DIMN), (const char*)(Alo + (size_t)m0 * DIMN),
                            (const char*)(Bhi + (size_t)n0 * DIMN), (const char*)(Blo + (size_t)n0 * DIMN) };

    #define GPL(s, sel) (1024u + (uint32_t)(s) * 65536u + (uint32_t)(sel) * 16384u)

    #pragma unroll
    for (int i = 0; i < 16; i++) {
        const int sel = i >> 2;
        const int cidx = (i & 3) * 256 + tid;
        const int row = cidx >> 3, cc = (cidx & 7) * 16;
        CPA16(sb + GPL(0, sel) + SW(row * 128 + cc),
              srcs[sel] + (size_t)row * (DIMN * 2) + cc);
    }
    CPC();

    float c[4][4][4] = {};

    for (int ch = 0; ch < 12; ch++) {
        if (ch < 11) {
            const int kb = (ch + 1) * 128;
            const int s = (ch + 1) & 1;
            #pragma unroll
            for (int i = 0; i < 16; i++) {
                const int sel = i >> 2;
                const int cidx = (i & 3) * 256 + tid;
                const int row = cidx >> 3, cc = (cidx & 7) * 16;
                CPA16(sb + GPL(s, sel) + SW(row * 128 + cc),
                      srcs[sel] + (size_t)row * (DIMN * 2) + kb + cc);
            }
            CPC();
            CPW(1);
        } else {
            CPW(0);
        }
        __syncthreads();

        const uint32_t pA = sb + GPL(ch & 1, 0), pAl = sb + GPL(ch & 1, 1);
        const uint32_t pB = sb + GPL(ch & 1, 2), pBl = sb + GPL(ch & 1, 3);
        #pragma unroll
        for (int ks = 0; ks < 4; ks++) {
            const int kbyt = ks * 32;
            uint32_t aH[4][4], aL[4][4];
            #pragma unroll
            for (int mt = 0; mt < 4; mt++) {
                const int rb = wm * 64 + mt * 16;
                ldsm_x4(aH[mt], ldsm_addr(pA,  lane, rb, 128, kbyt));
                ldsm_x4(aL[mt], ldsm_addr(pAl, lane, rb, 128, kbyt));
            }
            uint32_t bH[4][2], bL[4][2];
            #pragma unroll
            for (int np = 0; np < 2; np++) {
                uint32_t t0[4], t1[4];
                const int rb = wn * 32 + np * 16;
                ldsm_x4(t0, ldsm_addr(pB,  lane, rb, 128, kbyt));
                ldsm_x4(t1, ldsm_addr(pBl, lane, rb, 128, kbyt));
                bH[2*np][0] = t0[0]; bH[2*np][1] = t0[2];
                bH[2*np+1][0] = t0[1]; bH[2*np+1][1] = t0[3];
                bL[2*np][0] = t1[0]; bL[2*np][1] = t1[2];
                bL[2*np+1][0] = t1[1]; bL[2*np+1][1] = t1[3];
            }
            #pragma unroll
            for (int mt = 0; mt < 4; mt++)
                #pragma unroll
                for (int nt = 0; nt < 4; nt++) {
                    mma_bf16(c[mt][nt], aH[mt], bH[nt]);
                    mma_bf16(c[mt][nt], aH[mt], bL[nt]);
                    mma_bf16(c[mt][nt], aL[mt], bH[nt]);
                }
        }
        __syncthreads();
    }

    #pragma unroll
    for (int mt = 0; mt < 4; mt++)
        #pragma unroll
        for (int nt = 0; nt < 4; nt++)
            #pragma unroll
            for (int i = 0; i < 4; i++) {
                const int m = m0 + wm * 64 + mt * 16 + gid + (i >> 1) * 8;
                const int n = n0 + wn * 32 + nt * 8 + t4 * 2 + (i & 1);
                float v = c[mt][nt][i] + bias[n];
                if (mode == 3) {
                    outf[(size_t)m * DIMN + n] = v;
                } else {
                    if (mode == 0) v *= QSCALE;
                    const int b = m >> 11, t = m & (TT - 1);
                    const int h = n / DK, d = n - h * DK;
                    size_t idx = (mode == 2)
                        ? ((size_t)(b * NH + h) * DK + d) * TT + t
                        : ((size_t)(b * NH + h) * TT + t) * DK + d;
                    float hf = bf16round(v);
                    ohi[idx] = __float2bfloat16(hf);
                    olo[idx] = __float2bfloat16(v - hf);
                }
            }
}

// ---------------- pipelined mma flash attention (KTILE=64, 2 CTAs/SM) ------
// smem: rsum[128][2] @0; Q hi/lo @1024/@17408 (16KB each); KV stages @33792 (2 x 28KB)
//   stage: KH +0 (8K), KL +8192, VH +16384 (6K, pitch 128), VL +22528
#define ATTN_SMEM (33792 + 2*28672)
#define OST(s) (33792u + (uint32_t)(s) * 28672u)

__device__ __forceinline__ void stage_kv(uint32_t sb, uint32_t ost, int bh, int kt, int tid) {
    const char* kh = (const char*)(g_khi + ((size_t)bh * TT + kt * 64) * DK);
    const char* kl = (const char*)(g_klo + ((size_t)bh * TT + kt * 64) * DK);
    const char* vh = (const char*)(g_vthi + (size_t)bh * DK * TT + (size_t)kt * 64);
    const char* vl = (const char*)(g_vtlo + (size_t)bh * DK * TT + (size_t)kt * 64);
    #pragma unroll
    for (int i = 0; i < 6; i++) {
        const int id = i * 256 + tid;          // 0..1535
        if (id < 768) {                        // K planes: 64 rows x 96B (6 chunks)
            const char* src = (id < 384) ? kh : kl;
            const uint32_t dp = (id < 384) ? 0u : 8192u;
            const int c2 = (id < 384) ? id : id - 384;
            const int row = c2 / 6, cc = (c2 % 6) * 16;
            CPA16(sb + ost + dp + SW(row * 128 + cc), src + (size_t)row * (DK * 2) + cc);
        } else {                               // V^T planes: 48 rows x 128B (8 chunks)
            const int vid = id - 768;
            const char* src = (vid < 384) ? vh : vl;
            const uint32_t dp = (vid < 384) ? 16384u : 22528u;
            const int c2 = (vid < 384) ? vid : vid - 384;
            const int row = c2 >> 3, cc = (c2 & 7) * 16;
            CPA16(sb + ost + dp + SW(row * 128 + cc), src + (size_t)row * (TT * 2) + cc);
        }
    }
}

__global__ __launch_bounds__(256, 2)     // cap regs at 128 -> 2 CTAs/SM
void attn_mma()
{
    extern __shared__ char sm[];
    const uint32_t sm0 = smem_u32(sm);
    const uint32_t sb  = (sm0 + 1023) & ~1023u;
    char* sbase = sm + (sb - sm0);
    const uint32_t oQH = 1024, oQL = 17408;

    const int tid = threadIdx.x, wid = tid >> 5, lane = tid & 31;
    const int gid = lane >> 2, t4 = lane & 3;
    const int rg = wid & 3, cg = wid >> 2;
    const int bh = blockIdx.y, q0 = blockIdx.x * 128;
    const int b = bh >> 4, h = bh & 15;

    {
        const char* qh = (const char*)(g_qhi + ((size_t)bh * TT + q0) * DK);
        const char* ql = (const char*)(g_qlo + ((size_t)bh * TT + q0) * DK);
        #pragma unroll
        for (int i = 0; i < 6; i++) {
            const int id = i * 256 + tid;
            const char* src = (id < 768) ? qh : ql;
            const uint32_t dp = (id < 768) ? oQH : oQL;
            const int c2 = (id < 768) ? id : id - 768;
            const int row = c2 / 6, cc = (c2 % 6) * 16;
            CPA16(sb + dp + SW(row * 128 + cc), src + (size_t)row * (DK * 2) + cc);
        }
        stage_kv(sb, OST(0), bh, 0, tid);
        CPC();
    }

    float co[2][6][4] = {};
    float lsum[2][2] = {};

    for (int kt = 0; kt < 32; kt++) {
        if (kt < 31) {
            stage_kv(sb, OST((kt + 1) & 1), bh, kt + 1, tid);
            CPC();
            CPW(1);
        } else {
            CPW(0);
        }
        __syncthreads();

        const uint32_t oKH = sb + OST(kt & 1), oKL = oKH + 8192;
        const uint32_t oVH = oKH + 16384, oVL = oKH + 22528;

        // S = Q K^T over this warp's 32 keys
        float cs[2][4][4] = {};
        #pragma unroll
        for (int ks = 0; ks < 3; ks++) {
            const int kbyt = ks * 32;
            uint32_t qHf[2][4], qLf[2][4];
            #pragma unroll
            for (int mt = 0; mt < 2; mt++) {
                const int rb = rg * 32 + mt * 16;
                ldsm_x4(qHf[mt], ldsm_addr(sb + oQH, lane, rb, 128, kbyt));
                ldsm_x4(qLf[mt], ldsm_addr(sb + oQL, lane, rb, 128, kbyt));
            }
            #pragma unroll
            for (int np = 0; np < 2; np++) {
                uint32_t t0[4], t1[4];
                const int rb = cg * 32 + np * 16;
                ldsm_x4(t0, ldsm_addr(oKH, lane, rb, 128, kbyt));
                ldsm_x4(t1, ldsm_addr(oKL, lane, rb, 128, kbyt));
                uint32_t bHf0[2] = { t0[0], t0[2] }, bHf1[2] = { t0[1], t0[3] };
                uint32_t bLf0[2] = { t1[0], t1[2] }, bLf1[2] = { t1[1], t1[3] };
                #pragma unroll
                for (int mt = 0; mt < 2; mt++) {
                    mma_bf16(cs[mt][2*np],   qHf[mt], bHf0);
                    mma_bf16(cs[mt][2*np],   qHf[mt], bLf0);
                    mma_bf16(cs[mt][2*np],   qLf[mt], bHf0);
                    mma_bf16(cs[mt][2*np+1], qHf[mt], bHf1);
                    mma_bf16(cs[mt][2*np+1], qHf[mt], bLf1);
                    mma_bf16(cs[mt][2*np+1], qLf[mt], bHf1);
                }
            }
        }

        // p = exp(s); row partial sums
        #pragma unroll
        for (int mt = 0; mt < 2; mt++)
            #pragma unroll
            for (int nt = 0; nt < 4; nt++)
                #pragma unroll
                for (int i = 0; i < 4; i++) {
                    float e = __expf(cs[mt][nt][i]);
                    cs[mt][nt][i] = e;
                    lsum[mt][i >> 1] += e;
                }

        // O += P V
        #pragma unroll
        for (int kk = 0; kk < 2; kk++) {
            uint32_t pH[2][4], pL[2][4];
            #pragma unroll
            for (int mt = 0; mt < 2; mt++)
                #pragma unroll
                for (int half = 0; half < 2; half++) {
                    const float e0 = cs[mt][2 * kk + half][0], e1 = cs[mt][2 * kk + half][1];
                    const float e2 = cs[mt][2 * kk + half][2], e3 = cs[mt][2 * kk + half][3];
                    const float h0 = bf16round(e0), h1 = bf16round(e1);
                    const float h2 = bf16round(e2), h3 = bf16round(e3);
                    pH[mt][half * 2 + 0] = pack_bf16x2(h0, h1);
                    pH[mt][half * 2 + 1] = pack_bf16x2(h2, h3);
                    pL[mt][half * 2 + 0] = pack_bf16x2(e0 - h0, e1 - h1);
                    pL[mt][half * 2 + 1] = pack_bf16x2(e2 - h2, e3 - h3);
                }
            const int kbyt = cg * 64 + kk * 32;
            #pragma unroll
            for (int np = 0; np < 3; np++) {
                uint32_t t0[4], t1[4];
                const int rb = np * 16;
                ldsm_x4(t0, ldsm_addr(oVH, lane, rb, 128, kbyt));
                ldsm_x4(t1, ldsm_addr(oVL, lane, rb, 128, kbyt));
                uint32_t vHf0[2] = { t0[0], t0[2] }, vHf1[2] = { t0[1], t0[3] };
                uint32_t vLf0[2] = { t1[0], t1[2] }, vLf1[2] = { t1[1], t1[3] };
                #pragma unroll
                for (int mt = 0; mt < 2; mt++) {
                    mma_bf16(co[mt][2*np],   pH[mt], vHf0);
                    mma_bf16(co[mt][2*np],   pH[mt], vLf0);
                    mma_bf16(co[mt][2*np],   pL[mt], vHf0);
                    mma_bf16(co[mt][2*np+1], pH[mt], vHf1);
                    mma_bf16(co[mt][2*np+1], pH[mt], vLf1);
                    mma_bf16(co[mt][2*np+1], pL[mt], vHf1);
                }
            }
        }
        __syncthreads();
    }

    // cross-warp reductions
    #pragma unroll
    for (int mt = 0; mt < 2; mt++)
        #pragma unroll
        for (int hf = 0; hf < 2; hf++) {
            float v = lsum[mt][hf];
            v += __shfl_xor_sync(0xffffffffu, v, 1);
            v += __shfl_xor_sync(0xffffffffu, v, 2);
            lsum[mt][hf] = v;
        }
    float* rsum = reinterpret_cast<float*>(sbase);            // [128][2]
    if (t4 == 0)
        #pragma unroll
        for (int mt = 0; mt < 2; mt++)
            #pragma unroll
            for (int hf = 0; hf < 2; hf++)
                rsum[(rg * 32 + mt * 16 + hf * 8 + gid) * 2 + cg] = lsum[mt][hf];

    float* osum = reinterpret_cast<float*>(sbase + OST(0));   // [128][48] = 24KB < 28KB stage
    if (cg == 1)
        #pragma unroll
        for (int mt = 0; mt < 2; mt++)
            #pragma unroll
            for (int nt = 0; nt < 6; nt++)
                #pragma unroll
                for (int i = 0; i < 4; i++) {
                    const int row = rg * 32 + mt * 16 + (i >> 1) * 8 + gid;
                    const int col = nt * 8 + t4 * 2 + (i & 1);
                    osum[row * 48 + col] = co[mt][nt][i];
                }
    __syncthreads();

    if (cg == 0)
        #pragma unroll
        for (int mt = 0; mt < 2; mt++)
            #pragma unroll
            for (int nt = 0; nt < 6; nt++)
                #pragma unroll
                for (int i = 0; i < 4; i++) {
                    const int row = rg * 32 + mt * 16 + (i >> 1) * 8 + gid;
                    const int col = nt * 8 + t4 * 2 + (i & 1);
                    const float inv = 1.0f / (rsum[row * 2] + rsum[row * 2 + 1]);
                    const float v = (co[mt][nt][i] + osum[row * 48 + col]) * inv;
                    const size_t idx = ((size_t)(b * TT + q0 + row)) * DIMN + h * DK + col;
                    const float hfv = bf16round(v);
                    g_ohi[idx] = __float2bfloat16(hfv);
                    g_olo[idx] = __float2bfloat16(v - hfv);
                }
}

// ---------------- host launch ----------------
extern "C" void kernel_launch(void* const* d_in, const int* in_sizes, int n_in,
                              void* d_out, int out_size)
{
    const float* x  = (const float*)d_in[0];
    const float* Wq = (const float*)d_in[1];  const float* bq = (const float*)d_in[2];
    const float* Wk = (const float*)d_in[3];  const float* bk = (const float*)d_in[4];
    const float* Wv = (const float*)d_in[5];  const float* bv = (const float*)d_in[6];
    const float* Wp = (const float*)d_in[7];  const float* bp = (const float*)d_in[8];
    float* out = (float*)d_out;

    bf16 *xhi,*xlo,*wthi,*wtlo,*qhi,*qlo,*khi,*klo,*vthi,*vtlo,*ohi,*olo;
    cudaGetSymbolAddress((void**)&xhi, g_xhi);   cudaGetSymbolAddress((void**)&xlo, g_xlo);
    cudaGetSymbolAddress((void**)&wthi, g_wthi); cudaGetSymbolAddress((void**)&wtlo, g_wtlo);
    cudaGetSymbolAddress((void**)&qhi, g_qhi);   cudaGetSymbolAddress((void**)&qlo, g_qlo);
    cudaGetSymbolAddress((void**)&khi, g_khi);   cudaGetSymbolAddress((void**)&klo, g_klo);
    cudaGetSymbolAddress((void**)&vthi, g_vthi); cudaGetSymbolAddress((void**)&vtlo, g_vtlo);
    cudaGetSymbolAddress((void**)&ohi, g_ohi);   cudaGetSymbolAddress((void**)&olo, g_olo);

    cudaFuncSetAttribute(gemm_mma, cudaFuncAttributeMaxDynamicSharedMemorySize, GEMM_SMEM);
    cudaFuncSetAttribute(attn_mma, cudaFuncAttributeMaxDynamicSharedMemorySize, ATTN_SMEM);

    split_x_kernel<<<MM * DIMN / 1024, 256>>>(x, xhi, xlo);
    dim3 wg(24, 24, 4), wb(32, 8);
    wsplit_kernel<<<wg, wb>>>(Wq, Wk, Wv, Wp, wthi, wtlo);

    dim3 qkv_grid(DIMN / 128, MM / 128, 3);
    gemm_mma<<<qkv_grid, 256, GEMM_SMEM>>>(xhi, xlo, wthi, wtlo,
                                           bq, bk, bv, -1, nullptr,
                                           qhi, qlo, khi, klo, vthi, vtlo);

    attn_mma<<<dim3(TT / 128, BH), 256, ATTN_SMEM>>>();

    const size_t WSZ = (size_t)DIMN * DIMN;
    dim3 proj_grid(DIMN / 128, MM / 128, 1);
    gemm_mma<<<proj_grid, 256, GEMM_SMEM>>>(ohi, olo, wthi + 3 * WSZ, wtlo + 3 * WSZ,
                                            bp, bp, bp, 3, out,
                                            nullptr, nullptr, nullptr, nullptr, nullptr, nullptr);
}